// round 1
// baseline (speedup 1.0000x reference)
#include <cuda_runtime.h>

#define TI 128
#define MAX_TILES 64

// Per-block partial sums (double). 64x64 tiles covers n up to 8192.
__device__ double g_part[MAX_TILES * MAX_TILES];

// Constants: SIGMA = 1 -> a = 1/sqrt(2), c = 2a/sqrt(pi), a^2 = 0.5, 2*a^2*c = c
#define A_CONST 0.70710678118654752f
#define C_CONST 0.79788456080286536f

__global__ void __launch_bounds__(TI) pair_kernel(
    const float* __restrict__ q, const float* __restrict__ r,
    const float* __restrict__ u, int n)
{
    __shared__ float sq[TI], sx[TI], sy[TI], sz[TI], sux[TI], suy[TI], suz[TI];

    const int tx = threadIdx.x;
    const int i  = blockIdx.x * TI + tx;
    const int j0 = blockIdx.y * TI;

    // Load j-tile into shared memory (padded entries are "inert": q=u=0, far away)
    {
        int j = j0 + tx;
        if (j < n) {
            sq[tx]  = q[j];
            sx[tx]  = r[3 * j + 0];
            sy[tx]  = r[3 * j + 1];
            sz[tx]  = r[3 * j + 2];
            sux[tx] = u[3 * j + 0];
            suy[tx] = u[3 * j + 1];
            suz[tx] = u[3 * j + 2];
        } else {
            sq[tx]  = 0.0f;
            sx[tx]  = 1.0e7f + (float)j;   // distinct, far
            sy[tx]  = 0.0f;
            sz[tx]  = 0.0f;
            sux[tx] = 0.0f; suy[tx] = 0.0f; suz[tx] = 0.0f;
        }
    }

    float qi, rix, riy, riz, uix, uiy, uiz;
    if (i < n) {
        qi  = q[i];
        rix = r[3 * i + 0]; riy = r[3 * i + 1]; riz = r[3 * i + 2];
        uix = u[3 * i + 0]; uiy = u[3 * i + 1]; uiz = u[3 * i + 2];
    } else {
        qi  = 0.0f;
        rix = 2.0e7f + (float)i; riy = 0.0f; riz = 0.0f;
        uix = 0.0f; uiy = 0.0f; uiz = 0.0f;
    }
    __syncthreads();

    double acc = 0.0;

    #pragma unroll 8
    for (int jj = 0; jj < TI; jj++) {
        float dx = sx[jj] - rix;
        float dy = sy[jj] - riy;
        float dz = sz[jj] - riz;
        float rsq = fmaf(dx, dx, fmaf(dy, dy, dz * dz));

        bool self = ((j0 + jj) == i);
        if (self) rsq = 1.0f;  // keep math finite; contribution masked below

        float rinv  = rsqrtf(rsq);
        float rr    = rsq * rinv;          // |r|
        float x     = A_CONST * rr;        // a*r
        // gauss = exp(-(a r)^2) = exp(-0.5 * rsq)
        float gauss = __expf(-0.5f * rsq);

        // Abramowitz-Stegun 7.1.26: erf(x) = 1 - t*poly(t)*exp(-x^2), x >= 0
        float t = __fdividef(1.0f, fmaf(0.3275911f, x, 1.0f));
        float poly = fmaf(t, fmaf(t, fmaf(t, fmaf(t, 1.061405429f, -1.453152027f),
                                          1.421413741f), -0.284496736f), 0.254829592f);
        float erfv = fmaf(-t * poly, gauss, 1.0f);

        float rinv2 = rinv * rinv;
        float e1 = erfv * rinv;            // erf / r          (f_qq)
        float e3 = e1 * rinv2;             // erf / r^3
        float cg = C_CONST * gauss;
        float g2 = cg * rinv2;             // c * gauss / r^2
        float s1 = e3 - g2;
        float s2 = fmaf(3.0f, e3, fmaf(-2.0f, g2, -cg));  // 3 e3 - 2 g2 - c*gauss

        float qj  = sq[jj];
        float udi = fmaf(uix, dx, fmaf(uiy, dy, uiz * dz));
        float udj = fmaf(sux[jj], dx, fmaf(suy[jj], dy, suz[jj] * dz));
        float uu  = fmaf(uix, sux[jj], fmaf(uiy, suy[jj], uiz * suz[jj]));

        // qq term
        float pair = (qi * qj) * e1;
        // qu term: -s1 * (q_j (u_i . d) - q_i (u_j . d))
        pair = fmaf(-s1, fmaf(qj, udi, -(qi * udj)), pair);
        // uu term: +s1 (u_i . u_j) - s2 (u_i . dhat)(u_j . dhat)
        pair = fmaf(s1, uu, pair);
        pair = fmaf(-s2, (udi * udj) * rinv2, pair);

        pair = self ? 0.0f : pair;
        acc += (double)pair;
    }

    // Block reduction (deterministic): warp shuffle then shared
    #pragma unroll
    for (int off = 16; off > 0; off >>= 1)
        acc += __shfl_down_sync(0xffffffffu, acc, off);

    __shared__ double warp_s[TI / 32];
    if ((tx & 31) == 0) warp_s[tx >> 5] = acc;
    __syncthreads();
    if (tx == 0) {
        double s = 0.0;
        #pragma unroll
        for (int w = 0; w < TI / 32; w++) s += warp_s[w];
        g_part[blockIdx.y * gridDim.x + blockIdx.x] = s;
    }
}

__global__ void reduce_kernel(float* out, int nparts)
{
    __shared__ double sh[256];
    double s = 0.0;
    for (int k = threadIdx.x; k < nparts; k += 256) s += g_part[k];
    sh[threadIdx.x] = s;
    __syncthreads();
    #pragma unroll
    for (int st = 128; st > 0; st >>= 1) {
        if (threadIdx.x < st) sh[threadIdx.x] += sh[threadIdx.x + st];
        __syncthreads();
    }
    if (threadIdx.x == 0) {
        // total = 0.5 * sum_{i != j} pair(i,j);  pot = total / (2*pi) * NORM_FACTOR
        const double SCALE = 0.5 * 90.0474 / 6.283185307179586476925286766559;
        out[0] = (float)(sh[0] * SCALE);
    }
}

extern "C" void kernel_launch(void* const* d_in, const int* in_sizes, int n_in,
                              void* d_out, int out_size)
{
    const float* q = (const float*)d_in[0];
    const float* r = (const float*)d_in[1];
    const float* u = (const float*)d_in[2];
    float* out = (float*)d_out;

    int n = in_sizes[0];
    int tiles = (n + TI - 1) / TI;
    if (tiles > MAX_TILES) tiles = MAX_TILES;  // safety (n <= 8192 expected)

    dim3 grid(tiles, tiles);
    pair_kernel<<<grid, TI>>>(q, r, u, n);
    reduce_kernel<<<1, 256>>>(out, tiles * tiles);
}

// round 2
// speedup vs baseline: 1.9676x; 1.9676x over previous
#include <cuda_runtime.h>

#define TI 128
#define MAX_TILES 64
#define MAX_P (MAX_TILES * (MAX_TILES + 1) / 2)

__device__ double       g_part[MAX_P];
__device__ unsigned int g_count;   // zero-initialized at load; reset by last block each launch

// SIGMA=1 -> a = 1/sqrt(2), a^2 = 0.5, c = 2a/sqrt(pi)
#define C_CONST 0.79788456080286536f

__global__ void __launch_bounds__(256) pair_kernel(
    const float* __restrict__ q, const float* __restrict__ r,
    const float* __restrict__ u, int n, int tiles, float outscale,
    float* __restrict__ out)
{
    // ---- decode triangular tile index: (bi, bj) with bi <= bj ----
    int p = blockIdx.x;
    int bi = 0;
    while (p >= tiles - bi) { p -= tiles - bi; bi++; }
    const int bj = bi + p;
    const bool diag = (bi == bj);

    __shared__ float4 s_rq[TI];  // (x, y, z, q) of j-particles
    __shared__ float4 s_u[TI];   // (ux, uy, uz, 0)

    const int tx   = threadIdx.x;
    const int il   = tx & (TI - 1);
    const int half = tx >> 7;               // 0 or 1: which half of the j-range
    const int i    = bi * TI + il;
    const int j0   = bj * TI;

    // Cooperative j-tile load: threads 0..127 load (r,q), 128..255 load u
    if (tx < TI) {
        int j = j0 + tx;
        float4 v;
        if (j < n) { v.x = r[3*j]; v.y = r[3*j+1]; v.z = r[3*j+2]; v.w = q[j]; }
        else       { v.x = 1.0e7f + (float)j; v.y = 0.f; v.z = 0.f; v.w = 0.f; }
        s_rq[tx] = v;
    } else {
        int jt = tx - TI;
        int j  = j0 + jt;
        float4 v;
        if (j < n) { v.x = u[3*j]; v.y = u[3*j+1]; v.z = u[3*j+2]; v.w = 0.f; }
        else       { v = make_float4(0.f, 0.f, 0.f, 0.f); }
        s_u[jt] = v;
    }

    float qi = 0.f, rix, riy = 0.f, riz = 0.f, uix = 0.f, uiy = 0.f, uiz = 0.f;
    if (i < n) {
        qi  = q[i];
        rix = r[3*i]; riy = r[3*i+1]; riz = r[3*i+2];
        uix = u[3*i]; uiy = u[3*i+1]; uiz = u[3*i+2];
    } else {
        rix = 2.0e7f + (float)i;   // far from everything, q=u=0 -> contributes 0
    }
    __syncthreads();

    double acc = 0.0;
    const int jbeg = half * (TI / 2);

    for (int g = 0; g < TI / 2; g += 8) {
        float facc = 0.0f;
        #pragma unroll
        for (int k = 0; k < 8; k++) {
            const int jj = jbeg + g + k;
            float4 rqj = s_rq[jj];
            float4 ujv = s_u[jj];

            float dx = rqj.x - rix;
            float dy = rqj.y - riy;
            float dz = rqj.z - riz;
            float rsq = fmaf(dx, dx, fmaf(dy, dy, dz * dz));

            bool self = ((j0 + jj) == i);
            if (self) rsq = 1.0f;            // keep math finite; masked below

            float rinv  = rsqrtf(rsq);
            float rr    = rsq * rinv;        // |r|
            float x     = 0.70710678118654752f * rr;  // a*|r|
            float gauss = __expf(-0.5f * rsq);        // exp(-(a r)^2)

            // Abramowitz-Stegun 7.1.26 (|err| < 1.5e-7), reuses gauss = e^{-x^2}
            float t = __fdividef(1.0f, fmaf(0.3275911f, x, 1.0f));
            float poly = fmaf(t, fmaf(t, fmaf(t, fmaf(t, 1.061405429f, -1.453152027f),
                                              1.421413741f), -0.284496736f), 0.254829592f);
            float erfv = fmaf(-t * poly, gauss, 1.0f);

            float rinv2 = rinv * rinv;
            float e1 = erfv * rinv;                       // erf/r
            float e3 = e1 * rinv2;                        // erf/r^3
            float cg = C_CONST * gauss;
            float g2 = cg * rinv2;                        // c*gauss/r^2
            float s1 = e3 - g2;
            float s2 = fmaf(3.0f, e3, fmaf(-2.0f, g2, -cg));

            float qj  = rqj.w;
            float udi = fmaf(uix, dx, fmaf(uiy, dy, uiz * dz));
            float udj = fmaf(ujv.x, dx, fmaf(ujv.y, dy, ujv.z * dz));
            float uu  = fmaf(uix, ujv.x, fmaf(uiy, ujv.y, uiz * ujv.z));

            float pair = (qi * qj) * e1;                          // qq
            pair = fmaf(-s1, fmaf(qj, udi, -(qi * udj)), pair);   // qu
            pair = fmaf(s1, uu, pair);                            // uu (iso)
            pair = fmaf(-s2, (udi * udj) * rinv2, pair);          // uu (aniso)

            pair = self ? 0.0f : pair;
            facc += pair;
        }
        acc += (double)facc;
    }

    if (diag) acc *= 0.5;   // diagonal tile counts each unordered pair twice

    // ---- deterministic block reduction (warp shuffle + shared) ----
    #pragma unroll
    for (int off = 16; off > 0; off >>= 1)
        acc += __shfl_down_sync(0xffffffffu, acc, off);

    __shared__ double warp_s[8];
    if ((tx & 31) == 0) warp_s[tx >> 5] = acc;
    __syncthreads();

    __shared__ bool isLast;
    if (tx == 0) {
        double s = 0.0;
        #pragma unroll
        for (int w = 0; w < 8; w++) s += warp_s[w];
        g_part[blockIdx.x] = s;
        __threadfence();
        unsigned c = atomicAdd(&g_count, 1u);
        isLast = (c == gridDim.x - 1);
    }
    __syncthreads();

    // ---- last block performs the final reduction (fixed order -> deterministic) ----
    if (isLast) {
        __threadfence();
        const int nP = gridDim.x;
        double s = 0.0;
        for (int k = tx; k < nP; k += 256) s += g_part[k];

        #pragma unroll
        for (int off = 16; off > 0; off >>= 1)
            s += __shfl_down_sync(0xffffffffu, s, off);

        __shared__ double fin_s[8];
        if ((tx & 31) == 0) fin_s[tx >> 5] = s;
        __syncthreads();
        if (tx == 0) {
            double tot = 0.0;
            #pragma unroll
            for (int w = 0; w < 8; w++) tot += fin_s[w];
            out[0] = (float)(tot * (double)outscale);
            g_count = 0;   // reset for next launch / graph replay
        }
    }
}

extern "C" void kernel_launch(void* const* d_in, const int* in_sizes, int n_in,
                              void* d_out, int out_size)
{
    const float* q = (const float*)d_in[0];
    const float* r = (const float*)d_in[1];
    const float* u = (const float*)d_in[2];
    float* out = (float*)d_out;

    int n = in_sizes[0];
    int tiles = (n + TI - 1) / TI;
    if (tiles > MAX_TILES) tiles = MAX_TILES;

    int nP = tiles * (tiles + 1) / 2;
    // pot = sum_{i<j} pair(i,j) / (2*pi) * NORM_FACTOR
    float outscale = (float)(90.0474 / 6.283185307179586476925286766559);

    pair_kernel<<<nP, 256>>>(q, r, u, n, tiles, outscale, out);
}